// round 10
// baseline (speedup 1.0000x reference)
#include <cuda_runtime.h>

#define BB 64
#define NN 2048
#define DIM 768
#define D4 (DIM / 4)             // 192 float4 per row
#define POOL 1024
#define PLEN 16
#define ROWS 128                 // rows per copy/mean block
#define CHUNKS (NN / ROWS)       // 16 partial chunks per batch
#define OUTROWS (2 * PLEN + NN)  // 2080
#define KPB 8                    // keys per sim block
#define NBLK (POOL / KPB)        // 128 sim blocks
#define EPS 1e-12f

// Static device scratch — referenced ONLY from device code. Zero-initialized
// at module load; all ticket counters self-reset so graph replays see 0.
__device__ float4 g_partial[BB * CHUNKS * D4];   // 3.1 MB chunked row-sums
__device__ float4 g_xnorm[BB * D4];
__device__ float4 g_res[BB * D4];
__device__ float2 g_part1[BB * NBLK];            // (val, idx-bits) partial argmax
__device__ float2 g_part2[BB * NBLK];
__device__ float  g_m1[BB];
__device__ float  g_m2[BB];
__device__ int    g_idx1[BB];
__device__ int    g_idx2[BB];
__device__ unsigned int g_cnt1[BB];              // per-batch tickets (copy_mean)
__device__ unsigned int g_cntA;                  // sim pass-0 ticket
__device__ unsigned int g_cntB;                  // sim pass-1 ticket

// ---------------------------------------------------------------------------
// K1: stream x_embed -> out rows [32,2080) via float4 + per-chunk column sums;
// the LAST chunk-block of each batch (ticket) reduces partials -> x_norm.
// grid = BB*CHUNKS (1024), block = 192.
// ---------------------------------------------------------------------------
__global__ __launch_bounds__(D4) void copy_mean_kernel(
    const float4* __restrict__ x, float4* __restrict__ out)
{
    int blk = blockIdx.x;
    int b = blk / CHUNKS;
    int k = blk % CHUNKS;
    int c = threadIdx.x;

    const float4* src = x   + ((size_t)b * NN + (size_t)k * ROWS) * D4 + c;
    float4*       dst = out + ((size_t)b * OUTROWS + 2 * PLEN + (size_t)k * ROWS) * D4 + c;

    float4 s = make_float4(0.f, 0.f, 0.f, 0.f);
    #pragma unroll 8
    for (int r = 0; r < ROWS; r++) {
        float4 v = src[(size_t)r * D4];
        s.x += v.x; s.y += v.y; s.z += v.z; s.w += v.w;
        dst[(size_t)r * D4] = v;
    }
    g_partial[((size_t)b * CHUNKS + k) * D4 + c] = s;

    // ticket: last block for this batch does the mean->norm reduce
    __threadfence();
    __syncthreads();
    __shared__ unsigned int s_tick;
    if (c == 0) s_tick = atomicAdd(&g_cnt1[b], 1u);
    __syncthreads();
    if (s_tick != CHUNKS - 1) return;
    __threadfence();   // acquire: make peers' partials visible

    float4 t = make_float4(0.f, 0.f, 0.f, 0.f);
    #pragma unroll
    for (int kk = 0; kk < CHUNKS; kk++) {
        float4 v = g_partial[((size_t)b * CHUNKS + kk) * D4 + c];
        t.x += v.x; t.y += v.y; t.z += v.z; t.w += v.w;
    }
    const float inv_n = 1.0f / NN;
    float4 m = make_float4(t.x * inv_n, t.y * inv_n, t.z * inv_n, t.w * inv_n);

    __shared__ float red[D4];
    red[c] = m.x * m.x + m.y * m.y + m.z * m.z + m.w * m.w;
    __syncthreads();
    if (c < 64) red[c] += red[c + 64] + red[c + 128];
    __syncthreads();
    for (int o = 32; o >= 1; o >>= 1) {
        if (c < o) red[c] += red[c + o];
        __syncthreads();
    }
    float inv = rsqrtf(fmaxf(red[0], EPS));
    g_xnorm[(size_t)b * D4 + c] = make_float4(m.x * inv, m.y * inv, m.z * inv, m.w * inv);

    if (c == 0) g_cnt1[b] = 0u;   // reset for next graph replay
}

// ---------------------------------------------------------------------------
// K2/K3: similarity + per-block partial argmax; the LAST block (ticket) does
// the final argmax for all 64 batches and (pass 0 only) the residual.
// grid = NBLK (128), block = 256 (8 warps x 8 batches).
// pass=0: queries=g_xnorm -> g_idx1/g_m1 + residual
// pass=1: queries=g_res   -> g_idx2/g_m2
// ---------------------------------------------------------------------------
__global__ __launch_bounds__(256) void sim_kernel(
    const float4* __restrict__ keys, const float4* __restrict__ pkey, int pass)
{
    int blk = blockIdx.x;
    int tid = threadIdx.x;
    int lane = tid & 31;
    int w = tid >> 5;

    __shared__ float4 kk[KPB][D4];     // 24 KB
    __shared__ float  inv[KPB];

    for (int i = tid; i < KPB * D4; i += 256) {
        int kr = i / D4, cc = i % D4;
        kk[kr][cc] = keys[((size_t)blk * KPB + kr) * D4 + cc];
    }
    __syncthreads();

    // warp w: inverse norm of key w
    {
        float s = 0.f;
        #pragma unroll
        for (int j = 0; j < 6; j++) {
            float4 v = kk[w][lane + j * 32];
            s += v.x * v.x + v.y * v.y + v.z * v.z + v.w * v.w;
        }
        #pragma unroll
        for (int o = 16; o; o >>= 1) s += __shfl_xor_sync(0xffffffffu, s, o);
        if (lane == 0) inv[w] = rsqrtf(fmaxf(s, EPS));
    }
    __syncthreads();

    const float4* xbase = (pass == 0) ? g_xnorm : g_res;
    float2* part = (pass == 0) ? g_part1 : g_part2;

    #pragma unroll
    for (int bi = 0; bi < 8; bi++) {
        int b = w * 8 + bi;
        const float4* xr = xbase + (size_t)b * D4;
        float4 q[6];
        #pragma unroll
        for (int j = 0; j < 6; j++) q[j] = xr[lane + j * 32];

        float best = -1e30f; int bp = 0;
        #pragma unroll
        for (int kr = 0; kr < KPB; kr++) {
            float s = 0.f;
            #pragma unroll
            for (int j = 0; j < 6; j++) {
                float4 k = kk[kr][lane + j * 32];
                s += q[j].x * k.x + q[j].y * k.y + q[j].z * k.z + q[j].w * k.w;
            }
            #pragma unroll
            for (int o = 16; o; o >>= 1) s += __shfl_xor_sync(0xffffffffu, s, o);
            s *= inv[kr];
            if (s > best) { best = s; bp = blk * KPB + kr; }  // ascending -> lowest idx
        }
        if (lane == 0) {
            float2 pr; pr.x = best; pr.y = __int_as_float(bp);
            part[(size_t)b * NBLK + blk] = pr;
        }
    }

    // ---- ticket: last sim block finalizes argmax (+ residual on pass 0) ----
    __threadfence();
    __syncthreads();
    __shared__ unsigned int s_tick;
    if (tid == 0) s_tick = atomicAdd(pass == 0 ? &g_cntA : &g_cntB, 1u);
    __syncthreads();
    if (s_tick != NBLK - 1) return;
    __threadfence();

    __shared__ int s_id[BB];

    // warp w handles batches w*8 .. w*8+7; lane owns 4 of the 128 partials
    #pragma unroll
    for (int bi = 0; bi < 8; bi++) {
        int b = w * 8 + bi;
        float best = -1e30f; int bp = 0x7fffffff;
        #pragma unroll
        for (int j = 0; j < NBLK / 32; j++) {        // ascending block index
            float2 pr = part[(size_t)b * NBLK + lane + j * 32];
            float v = pr.x; int p = __float_as_int(pr.y);
            if (v > best || (v == best && p < bp)) { best = v; bp = p; }
        }
        #pragma unroll
        for (int o = 16; o; o >>= 1) {
            float v = __shfl_xor_sync(0xffffffffu, best, o);
            int   p = __shfl_xor_sync(0xffffffffu, bp, o);
            if (v > best || (v == best && p < bp)) { best = v; bp = p; }
        }
        if (lane == 0) {
            s_id[b] = bp;
            if (pass == 0) { g_idx1[b] = bp; g_m1[b] = best; }
            else           { g_idx2[b] = bp; g_m2[b] = best; }
        }
    }
    __syncthreads();

    if (pass == 0) {
        // residual = prompt_key[idx1] - x_norm, all 64 batches
        #pragma unroll
        for (int bi = 0; bi < 8; bi++) {
            int b = w * 8 + bi;
            int id = s_id[b];
            #pragma unroll
            for (int j = 0; j < 6; j++) {
                int c = lane + j * 32;
                float4 kv = pkey[(size_t)id * D4 + c];
                float4 xv = g_xnorm[(size_t)b * D4 + c];
                g_res[(size_t)b * D4 + c] =
                    make_float4(kv.x - xv.x, kv.y - xv.y, kv.z - xv.z, kv.w - xv.w);
            }
        }
    }

    if (tid == 0) { if (pass == 0) g_cntA = 0u; else g_cntB = 0u; }
}

// ---------------------------------------------------------------------------
// K4: gather selected prompt tiles into out rows [0,32) + write scalar.
// grid = BB*4 (256 blocks, 4 per batch), block = 256.
// ---------------------------------------------------------------------------
__global__ __launch_bounds__(256) void gather_kernel(
    const float4* __restrict__ prompt, const float4* __restrict__ rprompt,
    float4* __restrict__ out, int write_scalar, size_t scalar_off)
{
    int b = blockIdx.x >> 2;
    int q = blockIdx.x & 3;
    int tid = threadIdx.x;

    const int TOT = PLEN * D4;                 // 3072 float4 per tile
    const float4* src1 = rprompt + (size_t)g_idx2[b] * TOT;  // rows 0..15
    const float4* src2 = prompt  + (size_t)g_idx1[b] * TOT;  // rows 16..31
    float4* dst = out + (size_t)b * OUTROWS * D4;

    // this block handles quarter q of the 2*TOT float4s for batch b
    const int QUARTER = (2 * TOT) / 4;         // 1536
    int base = q * QUARTER;
    #pragma unroll
    for (int j = 0; j < QUARTER / 256; j++) {  // 6 iterations
        int i = base + tid + j * 256;
        float4 v = (i < TOT) ? src1[i] : src2[i - TOT];
        dst[i] = v;
    }

    if (write_scalar && blockIdx.x == 0 && tid == 0) {
        float total = 0.f;
        #pragma unroll
        for (int bb = 0; bb < BB; bb++) total += g_m1[bb] + g_m2[bb];
        ((float*)out)[scalar_off] = total * (1.0f / BB);
    }
}

// ---------------------------------------------------------------------------
extern "C" void kernel_launch(void* const* d_in, const int* in_sizes, int n_in,
                              void* d_out, int out_size)
{
    const float4* x       = (const float4*)d_in[0];
    const float4* prompt  = (const float4*)d_in[1];
    const float4* pkey4   = (const float4*)d_in[2];
    const float4* rprompt = (const float4*)d_in[3];
    const float4* rkey4   = (const float4*)d_in[4];
    float4* out = (float4*)d_out;

    copy_mean_kernel<<<BB * CHUNKS, D4>>>(x, out);
    sim_kernel<<<NBLK, 256>>>(pkey4, pkey4, 0);
    sim_kernel<<<NBLK, 256>>>(rkey4, pkey4, 1);

    long long prompted_elems = (long long)BB * OUTROWS * DIM;  // 102,236,160
    int write_scalar = ((long long)out_size > prompted_elems) ? 1 : 0;
    gather_kernel<<<BB * 4, 256>>>(prompt, rprompt, out, write_scalar,
                                   (size_t)prompted_elems);
}

// round 11
// speedup vs baseline: 1.1717x; 1.1717x over previous
#include <cuda_runtime.h>

#define BB 64
#define NN 2048
#define DIM 768
#define D4 (DIM / 4)             // 192 float4 per row
#define POOL 1024
#define PLEN 16
#define ROWS 128                 // rows per copy/mean block
#define CHUNKS (NN / ROWS)       // 16 partial chunks per batch
#define OUTROWS (2 * PLEN + NN)  // 2080
#define KPB 8                    // keys per sim block
#define NBLK (POOL / KPB)        // 128 sim blocks
#define EPS 1e-12f

// Static device scratch — referenced ONLY from device code. Zero-initialized
// at module load; ticket counters self-reset so graph replays see 0.
__device__ float4 g_partial[BB * CHUNKS * D4];   // 3.1 MB chunked row-sums
__device__ float4 g_xnorm[BB * D4];
__device__ float4 g_res[BB * D4];
__device__ float2 g_part1[BB * NBLK];            // (val, idx-bits) partial argmax
__device__ float2 g_part2[BB * NBLK];
__device__ float  g_m1[BB];
__device__ float  g_m2[BB];
__device__ int    g_idx1[BB];
__device__ int    g_idx2[BB];
__device__ unsigned int g_cntA;                  // sim pass-0 ticket
__device__ unsigned int g_cntB;                  // sim pass-1 ticket

// ---------------------------------------------------------------------------
// K1: stream x_embed -> out rows [32,2080) via float4, accumulating per-chunk
// column sums. grid = BB*CHUNKS (1024), block = 192. (R9 version: NO fence.)
// ---------------------------------------------------------------------------
__global__ __launch_bounds__(D4) void copy_mean_kernel(
    const float4* __restrict__ x, float4* __restrict__ out)
{
    int blk = blockIdx.x;
    int b = blk / CHUNKS;
    int k = blk % CHUNKS;
    int c = threadIdx.x;

    const float4* src = x   + ((size_t)b * NN + (size_t)k * ROWS) * D4 + c;
    float4*       dst = out + ((size_t)b * OUTROWS + 2 * PLEN + (size_t)k * ROWS) * D4 + c;

    float4 s = make_float4(0.f, 0.f, 0.f, 0.f);
    #pragma unroll 8
    for (int r = 0; r < ROWS; r++) {
        float4 v = src[(size_t)r * D4];
        s.x += v.x; s.y += v.y; s.z += v.z; s.w += v.w;
        dst[(size_t)r * D4] = v;
    }
    g_partial[((size_t)b * CHUNKS + k) * D4 + c] = s;
}

// ---------------------------------------------------------------------------
// K2: reduce chunked partials -> mean -> x_norm. grid = BB, block = 192.
// ---------------------------------------------------------------------------
__global__ __launch_bounds__(D4) void xnorm_kernel()
{
    int b = blockIdx.x;
    int c = threadIdx.x;

    float4 s = make_float4(0.f, 0.f, 0.f, 0.f);
    #pragma unroll
    for (int k = 0; k < CHUNKS; k++) {
        float4 v = g_partial[((size_t)b * CHUNKS + k) * D4 + c];
        s.x += v.x; s.y += v.y; s.z += v.z; s.w += v.w;
    }
    const float inv_n = 1.0f / NN;
    float4 m = make_float4(s.x * inv_n, s.y * inv_n, s.z * inv_n, s.w * inv_n);

    __shared__ float red[D4];
    red[c] = m.x * m.x + m.y * m.y + m.z * m.z + m.w * m.w;
    __syncthreads();
    if (c < 64) red[c] += red[c + 64] + red[c + 128];
    __syncthreads();
    for (int o = 32; o >= 1; o >>= 1) {
        if (c < o) red[c] += red[c + o];
        __syncthreads();
    }
    float inv = rsqrtf(fmaxf(red[0], EPS));
    g_xnorm[(size_t)b * D4 + c] = make_float4(m.x * inv, m.y * inv, m.z * inv, m.w * inv);
}

// ---------------------------------------------------------------------------
// K3/K4: similarity + per-block partial argmax; the LAST block (ticket, tiny
// store footprint -> cheap fence) finalizes the argmax for all 64 batches and
// (pass 0 only) computes the residual.
// grid = NBLK (128), block = 256 (8 warps x 8 batches).
// ---------------------------------------------------------------------------
__global__ __launch_bounds__(256) void sim_kernel(
    const float4* __restrict__ keys, const float4* __restrict__ pkey, int pass)
{
    int blk = blockIdx.x;
    int tid = threadIdx.x;
    int lane = tid & 31;
    int w = tid >> 5;

    __shared__ float4 kk[KPB][D4];     // 24 KB
    __shared__ float  inv[KPB];

    for (int i = tid; i < KPB * D4; i += 256) {
        int kr = i / D4, cc = i % D4;
        kk[kr][cc] = keys[((size_t)blk * KPB + kr) * D4 + cc];
    }
    __syncthreads();

    // warp w: inverse norm of key w
    {
        float s = 0.f;
        #pragma unroll
        for (int j = 0; j < 6; j++) {
            float4 v = kk[w][lane + j * 32];
            s += v.x * v.x + v.y * v.y + v.z * v.z + v.w * v.w;
        }
        #pragma unroll
        for (int o = 16; o; o >>= 1) s += __shfl_xor_sync(0xffffffffu, s, o);
        if (lane == 0) inv[w] = rsqrtf(fmaxf(s, EPS));
    }
    __syncthreads();

    const float4* xbase = (pass == 0) ? g_xnorm : g_res;
    float2* part = (pass == 0) ? g_part1 : g_part2;

    #pragma unroll
    for (int bi = 0; bi < 8; bi++) {
        int b = w * 8 + bi;
        const float4* xr = xbase + (size_t)b * D4;
        float4 q[6];
        #pragma unroll
        for (int j = 0; j < 6; j++) q[j] = xr[lane + j * 32];

        float best = -1e30f; int bp = 0;
        #pragma unroll
        for (int kr = 0; kr < KPB; kr++) {
            float s = 0.f;
            #pragma unroll
            for (int j = 0; j < 6; j++) {
                float4 k = kk[kr][lane + j * 32];
                s += q[j].x * k.x + q[j].y * k.y + q[j].z * k.z + q[j].w * k.w;
            }
            #pragma unroll
            for (int o = 16; o; o >>= 1) s += __shfl_xor_sync(0xffffffffu, s, o);
            s *= inv[kr];
            if (s > best) { best = s; bp = blk * KPB + kr; }  // ascending -> lowest idx
        }
        if (lane == 0) {
            float2 pr; pr.x = best; pr.y = __int_as_float(bp);
            part[(size_t)b * NBLK + blk] = pr;
        }
    }

    // ---- ticket: last sim block finalizes argmax (+ residual on pass 0) ----
    // Only ~512 B of stores in flight per block here, so the fence is cheap.
    __threadfence();
    __syncthreads();
    __shared__ unsigned int s_tick;
    if (tid == 0) s_tick = atomicAdd(pass == 0 ? &g_cntA : &g_cntB, 1u);
    __syncthreads();
    if (s_tick != NBLK - 1) return;
    __threadfence();   // acquire: peers' partials visible

    __shared__ int s_id[BB];

    #pragma unroll
    for (int bi = 0; bi < 8; bi++) {
        int b = w * 8 + bi;
        float best = -1e30f; int bp = 0x7fffffff;
        #pragma unroll
        for (int j = 0; j < NBLK / 32; j++) {        // ascending block index
            float2 pr = part[(size_t)b * NBLK + lane + j * 32];
            float v = pr.x; int p = __float_as_int(pr.y);
            if (v > best || (v == best && p < bp)) { best = v; bp = p; }
        }
        #pragma unroll
        for (int o = 16; o; o >>= 1) {
            float v = __shfl_xor_sync(0xffffffffu, best, o);
            int   p = __shfl_xor_sync(0xffffffffu, bp, o);
            if (v > best || (v == best && p < bp)) { best = v; bp = p; }
        }
        if (lane == 0) {
            s_id[b] = bp;
            if (pass == 0) { g_idx1[b] = bp; g_m1[b] = best; }
            else           { g_idx2[b] = bp; g_m2[b] = best; }
        }
    }
    __syncthreads();

    if (pass == 0) {
        // residual = prompt_key[idx1] - x_norm, all 64 batches
        #pragma unroll
        for (int bi = 0; bi < 8; bi++) {
            int b = w * 8 + bi;
            int id = s_id[b];
            #pragma unroll
            for (int j = 0; j < 6; j++) {
                int c = lane + j * 32;
                float4 kv = pkey[(size_t)id * D4 + c];
                float4 xv = g_xnorm[(size_t)b * D4 + c];
                g_res[(size_t)b * D4 + c] =
                    make_float4(kv.x - xv.x, kv.y - xv.y, kv.z - xv.z, kv.w - xv.w);
            }
        }
    }

    if (tid == 0) { if (pass == 0) g_cntA = 0u; else g_cntB = 0u; }
}

// ---------------------------------------------------------------------------
// K5: gather selected prompt tiles into out rows [0,32) + write scalar.
// grid = BB*4 (256 blocks, 4 per batch), block = 256.
// ---------------------------------------------------------------------------
__global__ __launch_bounds__(256) void gather_kernel(
    const float4* __restrict__ prompt, const float4* __restrict__ rprompt,
    float4* __restrict__ out, int write_scalar, size_t scalar_off)
{
    int b = blockIdx.x >> 2;
    int q = blockIdx.x & 3;
    int tid = threadIdx.x;

    const int TOT = PLEN * D4;                 // 3072 float4 per tile
    const float4* src1 = rprompt + (size_t)g_idx2[b] * TOT;  // rows 0..15
    const float4* src2 = prompt  + (size_t)g_idx1[b] * TOT;  // rows 16..31
    float4* dst = out + (size_t)b * OUTROWS * D4;

    const int QUARTER = (2 * TOT) / 4;         // 1536
    int base = q * QUARTER;
    #pragma unroll
    for (int j = 0; j < QUARTER / 256; j++) {  // 6 iterations
        int i = base + tid + j * 256;
        float4 v = (i < TOT) ? src1[i] : src2[i - TOT];
        dst[i] = v;
    }

    if (write_scalar && blockIdx.x == 0 && tid == 0) {
        float total = 0.f;
        #pragma unroll
        for (int bb = 0; bb < BB; bb++) total += g_m1[bb] + g_m2[bb];
        ((float*)out)[scalar_off] = total * (1.0f / BB);
    }
}

// ---------------------------------------------------------------------------
extern "C" void kernel_launch(void* const* d_in, const int* in_sizes, int n_in,
                              void* d_out, int out_size)
{
    const float4* x       = (const float4*)d_in[0];
    const float4* prompt  = (const float4*)d_in[1];
    const float4* pkey4   = (const float4*)d_in[2];
    const float4* rprompt = (const float4*)d_in[3];
    const float4* rkey4   = (const float4*)d_in[4];
    float4* out = (float4*)d_out;

    copy_mean_kernel<<<BB * CHUNKS, D4>>>(x, out);
    xnorm_kernel<<<BB, D4>>>();
    sim_kernel<<<NBLK, 256>>>(pkey4, pkey4, 0);
    sim_kernel<<<NBLK, 256>>>(rkey4, pkey4, 1);

    long long prompted_elems = (long long)BB * OUTROWS * DIM;  // 102,236,160
    int write_scalar = ((long long)out_size > prompted_elems) ? 1 : 0;
    gather_kernel<<<BB * 4, 256>>>(prompt, rprompt, out, write_scalar,
                                   (size_t)prompted_elems);
}